// round 11
// baseline (speedup 1.0000x reference)
#include <cuda_runtime.h>

#define N_NODES 100000
#define N_EDGES 1600000
#define E_TOT   (N_EDGES + N_NODES)   // with self loops
#define HID     64
#define OUT_CH  16

// exp(-2*T), T = 1.0
#define EN2 0.1353352832366127f

// ---------------- scratch (static device globals; no allocs allowed) ----------
__device__ float g_h1[(size_t)N_NODES * HID];      // layer-1 linear output
__device__ float g_out1[(size_t)N_NODES * HID];    // layer-1 aggregated output
__device__ float g_h2[(size_t)N_NODES * OUT_CH];   // layer-2 linear output
__device__ float2 g_w[N_NODES];                    // (w_pos, w_neg) per source node
__device__ int g_pos[N_NODES];
__device__ int g_tot[N_NODES];
__device__ unsigned char g_sign[E_TOT];
__device__ int g_st;                               // 1 = int32 edge data, 2 = int64

// ---------------- dtype detection: int32 vs int64 edge_index -----------------
// int64 little-endian with values < 2^31 => every odd int32 word is 0.
// int32 => odd words are edge ids, ~always nonzero.
__global__ void k_detect(const int* __restrict__ e32) {
    if (threadIdx.x == 0 && blockIdx.x == 0) {
        int nz = 0;
        for (int i = 1; i < 2048; i += 2) nz += (e32[i] != 0);
        g_st = (nz > 16) ? 1 : 2;
    }
}

// ---------------- GEMM1: h1 = x @ W1^T  (64 -> 64) ---------------------------
__global__ __launch_bounds__(256) void k_gemm64(const float* __restrict__ x,
                                                const float* __restrict__ W) {
    __shared__ float Ws[64][65];
    int t = threadIdx.x;
    for (int i = t; i < 64 * 64; i += 256) Ws[i >> 6][i & 63] = W[i];
    __syncthreads();
    int idx = blockIdx.x * 256 + t;       // N*64 total, divisible by 256
    int n = idx >> 6, o = idx & 63;
    const float* xr = x + (size_t)n * 64;
    float acc = 0.f;
#pragma unroll
    for (int i = 0; i < 64; i++) acc = fmaf(xr[i], Ws[o][i], acc);
    g_h1[idx] = acc;
}

// ---------------- GEMM2: h2 = relu(out1 + b1) @ W2^T  (64 -> 16) -------------
__global__ __launch_bounds__(256) void k_gemm16(const float* __restrict__ b1,
                                                const float* __restrict__ W2) {
    __shared__ float Ws[16][65];
    __shared__ float bs[64];
    int t = threadIdx.x;
    for (int i = t; i < 16 * 64; i += 256) Ws[i >> 6][i & 63] = W2[i];
    if (t < 64) bs[t] = b1[t];
    __syncthreads();
    int idx = blockIdx.x * 256 + t;       // N*16 total, divisible by 256
    int n = idx >> 4, o = idx & 15;
    const float* hr = g_out1 + (size_t)n * 64;
    float acc = 0.f;
#pragma unroll
    for (int i = 0; i < 64; i++) {
        float v = hr[i] + bs[i];
        v = v > 0.f ? v : 0.f;
        acc = fmaf(v, Ws[o][i], acc);
    }
    g_h2[idx] = acc;
}

// ---------------- per-edge sign + per-source counts, C=64 (warp/edge) --------
__global__ __launch_bounds__(256) void k_sign64(const int* __restrict__ e32) {
    int gid = blockIdx.x * 256 + threadIdx.x;
    int e = gid >> 5;
    if (e >= E_TOT) return;               // whole warp exits together
    int lane = threadIdx.x & 31;
    int src, dst;
    if (e < N_EDGES) {
        int st = g_st;
        src = e32[e * st];
        dst = e32[(N_EDGES + e) * st];
    } else {
        src = e - N_EDGES; dst = src;
    }
    const float* hs = g_h1 + (size_t)src * 64;
    const float* hd = g_h1 + (size_t)dst * 64;
    float p = hs[lane] * hd[lane] + hs[lane + 32] * hd[lane + 32];
#pragma unroll
    for (int off = 16; off; off >>= 1) p += __shfl_xor_sync(0xffffffffu, p, off);
    if (lane == 0) {
        int s = (p > 0.f) ? 1 : 0;
        g_sign[e] = (unsigned char)s;
        atomicAdd(&g_tot[src], 1);
        if (s) atomicAdd(&g_pos[src], 1);
    }
}

// ---------------- per-node softmax coefficients ------------------------------
__global__ __launch_bounds__(256) void k_coef() {
    int n = blockIdx.x * 256 + threadIdx.x;
    if (n >= N_NODES) return;
    int p = g_pos[n], t = g_tot[n];
    float wp, wn;
    if (p > 0) {
        float d = (float)p + (float)(t - p) * EN2;
        wp = 1.f / d;
        wn = EN2 / d;
    } else {
        wp = 0.f;
        wn = 1.f / (float)t;
    }
    g_w[n] = make_float2(wp, wn);
}

// ---------------- scatter messages, C=64 (warp/edge) -------------------------
__global__ __launch_bounds__(256) void k_scat64(const int* __restrict__ e32) {
    int gid = blockIdx.x * 256 + threadIdx.x;
    int e = gid >> 5;
    if (e >= E_TOT) return;
    int lane = threadIdx.x & 31;
    int src, dst;
    if (e < N_EDGES) {
        int st = g_st;
        src = e32[e * st];
        dst = e32[(N_EDGES + e) * st];
    } else {
        src = e - N_EDGES; dst = src;
    }
    float2 w2 = g_w[src];
    float w = g_sign[e] ? w2.x : w2.y;
    const float* hs = g_h1 + (size_t)src * 64;
    float* o = g_out1 + (size_t)dst * 64;
    atomicAdd(&o[lane],      hs[lane]      * w);
    atomicAdd(&o[lane + 32], hs[lane + 32] * w);
}

// ---------------- per-edge sign + counts, C=16 (half-warp/edge) --------------
__global__ __launch_bounds__(256) void k_sign16(const int* __restrict__ e32) {
    int gid = blockIdx.x * 256 + threadIdx.x;
    int lane = threadIdx.x & 31;
    int e = (gid >> 5) * 2 + (lane >> 4);
    int l16 = lane & 15;
    bool valid = (e < E_TOT);
    int src = 0, dst = 0;
    if (valid) {
        if (e < N_EDGES) {
            int st = g_st;
            src = e32[e * st];
            dst = e32[(N_EDGES + e) * st];
        } else {
            src = e - N_EDGES; dst = src;
        }
    }
    const float* hs = g_h2 + (size_t)src * 16;
    const float* hd = g_h2 + (size_t)dst * 16;
    float p = valid ? hs[l16] * hd[l16] : 0.f;
#pragma unroll
    for (int off = 8; off; off >>= 1) p += __shfl_xor_sync(0xffffffffu, p, off);
    if (valid && l16 == 0) {
        int s = (p > 0.f) ? 1 : 0;
        g_sign[e] = (unsigned char)s;
        atomicAdd(&g_tot[src], 1);
        if (s) atomicAdd(&g_pos[src], 1);
    }
}

// ---------------- scatter messages, C=16 -> d_out ----------------------------
__global__ __launch_bounds__(256) void k_scat16(const int* __restrict__ e32,
                                                float* __restrict__ out) {
    int gid = blockIdx.x * 256 + threadIdx.x;
    int lane = threadIdx.x & 31;
    int e = (gid >> 5) * 2 + (lane >> 4);
    int l16 = lane & 15;
    if (e >= E_TOT) return;
    int src, dst;
    if (e < N_EDGES) {
        int st = g_st;
        src = e32[e * st];
        dst = e32[(N_EDGES + e) * st];
    } else {
        src = e - N_EDGES; dst = src;
    }
    float2 w2 = g_w[src];
    float w = g_sign[e] ? w2.x : w2.y;
    atomicAdd(&out[(size_t)dst * 16 + l16], g_h2[(size_t)src * 16 + l16] * w);
}

// ---------------- final: add b2 + log_softmax, in place in d_out -------------
__global__ __launch_bounds__(256) void k_final(const float* __restrict__ b2,
                                               float* __restrict__ out) {
    int n = blockIdx.x * 256 + threadIdx.x;
    if (n >= N_NODES) return;
    float v[16];
    float m = -1e30f;
#pragma unroll
    for (int c = 0; c < 16; c++) {
        v[c] = out[(size_t)n * 16 + c] + b2[c];
        m = fmaxf(m, v[c]);
    }
    float s = 0.f;
#pragma unroll
    for (int c = 0; c < 16; c++) s += expf(v[c] - m);
    float lse = m + logf(s);
#pragma unroll
    for (int c = 0; c < 16; c++) out[(size_t)n * 16 + c] = v[c] - lse;
}

// -----------------------------------------------------------------------------
extern "C" void kernel_launch(void* const* d_in, const int* in_sizes, int n_in,
                              void* d_out, int out_size) {
    const float* x  = (const float*)d_in[0];
    const int*   e32 = (const int*)d_in[1];   // edge_index (int32 or int64 — detected)
    const float* W1 = (const float*)d_in[2];
    const float* b1 = (const float*)d_in[3];
    const float* W2 = (const float*)d_in[4];
    const float* b2 = (const float*)d_in[5];
    float* out = (float*)d_out;

    void *p_out1, *p_pos, *p_tot;
    cudaGetSymbolAddress(&p_out1, g_out1);
    cudaGetSymbolAddress(&p_pos, g_pos);
    cudaGetSymbolAddress(&p_tot, g_tot);

    const int EB   = (E_TOT * 32 + 255) / 256;             // warp per edge
    const int EB2  = (((E_TOT + 1) / 2) * 32 + 255) / 256; // 2 edges per warp
    const int NB   = (N_NODES + 255) / 256;

    k_detect<<<1, 32>>>(e32);

    // ---- layer 1 ----
    cudaMemsetAsync(p_out1, 0, sizeof(float) * (size_t)N_NODES * HID);
    cudaMemsetAsync(p_pos, 0, sizeof(int) * N_NODES);
    cudaMemsetAsync(p_tot, 0, sizeof(int) * N_NODES);

    k_gemm64<<<N_NODES * 64 / 256, 256>>>(x, W1);
    k_sign64<<<EB, 256>>>(e32);
    k_coef<<<NB, 256>>>();
    k_scat64<<<EB, 256>>>(e32);

    // ---- layer 2 ----
    k_gemm16<<<N_NODES * 16 / 256, 256>>>(b1, W2);

    cudaMemsetAsync(p_pos, 0, sizeof(int) * N_NODES);
    cudaMemsetAsync(p_tot, 0, sizeof(int) * N_NODES);
    cudaMemsetAsync(d_out, 0, sizeof(float) * (size_t)N_NODES * OUT_CH);

    k_sign16<<<EB2, 256>>>(e32);
    k_coef<<<NB, 256>>>();
    k_scat16<<<EB2, 256>>>(e32, out);
    k_final<<<NB, 256>>>(b2, out);
}

// round 13
// speedup vs baseline: 1.8028x; 1.8028x over previous
#include <cuda_runtime.h>

#define N_NODES 100000
#define N_EDGES 1600000
#define E_TOT   (N_EDGES + N_NODES)   // with self loops (1,700,000 — even)
#define HID     64
#define OUT_CH  16

// exp(-2*T), T = 1.0
#define EN2 0.1353352832366127f

// ---------------- scratch (static device globals; no allocs allowed) ----------
__device__ float4 g_h1[(size_t)N_NODES * 16];    // layer-1 linear output (64 f32 / node)
__device__ float4 g_out1[(size_t)N_NODES * 16];  // layer-1 aggregated output
__device__ float4 g_h2[(size_t)N_NODES * 4];     // layer-2 linear output (16 f32 / node)
__device__ float2 g_w[N_NODES];                  // (w_pos, w_neg) per source node
__device__ int g_pos[N_NODES];
__device__ int g_tot[N_NODES];
__device__ unsigned char g_sign[E_TOT];
__device__ int g_st;                             // 1 = int32 edge data, 2 = int64

// ---------------- helpers ----------------------------------------------------
__device__ __forceinline__ void edge_ld(const int* __restrict__ e32, int e, int st,
                                        int& src, int& dst) {
    if (e < N_EDGES) {
        src = e32[e * st];
        dst = e32[(N_EDGES + e) * st];
    } else {
        src = e - N_EDGES;
        dst = src;
    }
}

__device__ __forceinline__ void red_add_v4(float4* p, float4 v) {
    asm volatile("red.global.add.v4.f32 [%0], {%1, %2, %3, %4};"
                 :: "l"(p), "f"(v.x), "f"(v.y), "f"(v.z), "f"(v.w)
                 : "memory");
}

// ---------------- dtype detection: int32 vs int64 edge_index -----------------
__global__ void k_detect(const int* __restrict__ e32) {
    if (threadIdx.x == 0 && blockIdx.x == 0) {
        int nz = 0;
        for (int i = 1; i < 2048; i += 2) nz += (e32[i] != 0);
        g_st = (nz > 16) ? 1 : 2;
    }
}

// ---------------- GEMM1: h1 = x @ W1^T  (64 -> 64), float4 outputs -----------
__global__ __launch_bounds__(256) void k_gemm64(const float* __restrict__ x,
                                                const float* __restrict__ W) {
    __shared__ float Wt[64][68];             // Wt[i][o] = W[o][i]; 68 = pad (x4 aligned)
    int t = threadIdx.x;
    for (int s = t; s < 64 * 64; s += 256) {
        int o = s >> 6, i = s & 63;
        Wt[i][o] = W[s];                     // W row-major [o][i], coalesced read
    }
    __syncthreads();
    int idx = blockIdx.x * 256 + t;          // N*16 total, divisible by 256
    int n = idx >> 4, o4 = idx & 15;
    const float* xr = x + (size_t)n * 64;
    const float4* Wrow;
    float4 acc = make_float4(0.f, 0.f, 0.f, 0.f);
#pragma unroll
    for (int i = 0; i < 64; i++) {
        float xv = xr[i];                    // broadcast across half-warp
        float4 wv = ((const float4*)Wt[i])[o4];
        acc.x = fmaf(xv, wv.x, acc.x);
        acc.y = fmaf(xv, wv.y, acc.y);
        acc.z = fmaf(xv, wv.z, acc.z);
        acc.w = fmaf(xv, wv.w, acc.w);
    }
    (void)Wrow;
    g_h1[idx] = acc;
}

// ---------------- GEMM2: h2 = relu(out1 + b1) @ W2^T  (64 -> 16) -------------
__global__ __launch_bounds__(256) void k_gemm16(const float* __restrict__ b1,
                                                const float* __restrict__ W2) {
    __shared__ float Ws[16][65];
    __shared__ float bs[64];
    int t = threadIdx.x;
    for (int i = t; i < 16 * 64; i += 256) Ws[i >> 6][i & 63] = W2[i];
    if (t < 64) bs[t] = b1[t];
    __syncthreads();
    int idx = blockIdx.x * 256 + t;          // N*16 total, divisible by 256
    int n = idx >> 4, o = idx & 15;
    const float* hr = (const float*)(g_out1 + (size_t)n * 16);
    float acc = 0.f;
#pragma unroll
    for (int i = 0; i < 64; i++) {
        float v = hr[i] + bs[i];
        v = v > 0.f ? v : 0.f;
        acc = fmaf(v, Ws[o][i], acc);
    }
    ((float*)g_h2)[idx] = acc;
}

// ---------------- per-edge sign + per-source counts, C=64 (half-warp/edge) ---
__global__ __launch_bounds__(256) void k_sign64(const int* __restrict__ e32) {
    int gid = blockIdx.x * 256 + threadIdx.x;
    int lane = threadIdx.x & 31;
    int e = (gid >> 5) * 2 + (lane >> 4);    // E_TOT even => always in range
    int l16 = lane & 15;
    int st = g_st;
    int src, dst;
    edge_ld(e32, e, st, src, dst);
    float4 a = g_h1[(size_t)src * 16 + l16];
    float4 b = g_h1[(size_t)dst * 16 + l16];
    float p = a.x * b.x + a.y * b.y + a.z * b.z + a.w * b.w;
#pragma unroll
    for (int off = 8; off; off >>= 1) p += __shfl_xor_sync(0xffffffffu, p, off);
    if (l16 == 0) {
        int s = (p > 0.f) ? 1 : 0;
        g_sign[e] = (unsigned char)s;
        atomicAdd(&g_tot[src], 1);
        if (s) atomicAdd(&g_pos[src], 1);
    }
}

// ---------------- per-node softmax coefficients ------------------------------
__global__ __launch_bounds__(256) void k_coef() {
    int n = blockIdx.x * 256 + threadIdx.x;
    if (n >= N_NODES) return;
    int p = g_pos[n], t = g_tot[n];
    float wp, wn;
    if (p > 0) {
        float d = (float)p + (float)(t - p) * EN2;
        wp = 1.f / d;
        wn = EN2 / d;
    } else {
        wp = 0.f;
        wn = 1.f / (float)t;
    }
    g_w[n] = make_float2(wp, wn);
}

// ---------------- scatter messages, C=64 (half-warp/edge, RED.128) -----------
__global__ __launch_bounds__(256) void k_scat64(const int* __restrict__ e32) {
    int gid = blockIdx.x * 256 + threadIdx.x;
    int lane = threadIdx.x & 31;
    int e = (gid >> 5) * 2 + (lane >> 4);
    int l16 = lane & 15;
    int st = g_st;
    int src, dst;
    edge_ld(e32, e, st, src, dst);
    float2 w2 = g_w[src];
    float w = g_sign[e] ? w2.x : w2.y;
    float4 v = g_h1[(size_t)src * 16 + l16];
    v.x *= w; v.y *= w; v.z *= w; v.w *= w;
    red_add_v4(&g_out1[(size_t)dst * 16 + l16], v);
}

// ---------------- per-edge sign + counts, C=16 (4 lanes/edge) ----------------
__global__ __launch_bounds__(256) void k_sign16(const int* __restrict__ e32) {
    int gid = blockIdx.x * 256 + threadIdx.x;
    int lane = threadIdx.x & 31;
    int e = (gid >> 5) * 8 + (lane >> 2);
    int c = lane & 3;
    bool valid = (e < E_TOT);
    int st = g_st;
    int src = 0, dst = 0;
    if (valid) edge_ld(e32, e, st, src, dst);
    float4 a = g_h2[(size_t)src * 4 + c];
    float4 b = g_h2[(size_t)dst * 4 + c];
    float p = valid ? (a.x * b.x + a.y * b.y + a.z * b.z + a.w * b.w) : 0.f;
    p += __shfl_xor_sync(0xffffffffu, p, 1);
    p += __shfl_xor_sync(0xffffffffu, p, 2);
    if (valid && c == 0) {
        int s = (p > 0.f) ? 1 : 0;
        g_sign[e] = (unsigned char)s;
        atomicAdd(&g_tot[src], 1);
        if (s) atomicAdd(&g_pos[src], 1);
    }
}

// ---------------- scatter messages, C=16 -> d_out (RED.128) ------------------
__global__ __launch_bounds__(256) void k_scat16(const int* __restrict__ e32,
                                                float4* __restrict__ out) {
    int gid = blockIdx.x * 256 + threadIdx.x;
    int lane = threadIdx.x & 31;
    int e = (gid >> 5) * 8 + (lane >> 2);
    int c = lane & 3;
    if (e >= E_TOT) return;
    int st = g_st;
    int src, dst;
    edge_ld(e32, e, st, src, dst);
    float2 w2 = g_w[src];
    float w = g_sign[e] ? w2.x : w2.y;
    float4 v = g_h2[(size_t)src * 4 + c];
    v.x *= w; v.y *= w; v.z *= w; v.w *= w;
    red_add_v4(&out[(size_t)dst * 4 + c], v);
}

// ---------------- final: add b2 + log_softmax, in place in d_out -------------
__global__ __launch_bounds__(256) void k_final(const float* __restrict__ b2,
                                               float* __restrict__ out) {
    int n = blockIdx.x * 256 + threadIdx.x;
    if (n >= N_NODES) return;
    float v[16];
    float m = -1e30f;
#pragma unroll
    for (int c = 0; c < 16; c++) {
        v[c] = out[(size_t)n * 16 + c] + b2[c];
        m = fmaxf(m, v[c]);
    }
    float s = 0.f;
#pragma unroll
    for (int c = 0; c < 16; c++) s += expf(v[c] - m);
    float lse = m + logf(s);
#pragma unroll
    for (int c = 0; c < 16; c++) out[(size_t)n * 16 + c] = v[c] - lse;
}

// -----------------------------------------------------------------------------
extern "C" void kernel_launch(void* const* d_in, const int* in_sizes, int n_in,
                              void* d_out, int out_size) {
    const float* x   = (const float*)d_in[0];
    const int*   e32 = (const int*)d_in[1];   // edge_index (int32 or int64 — detected)
    const float* W1  = (const float*)d_in[2];
    const float* b1  = (const float*)d_in[3];
    const float* W2  = (const float*)d_in[4];
    const float* b2  = (const float*)d_in[5];
    float* out = (float*)d_out;

    void *p_out1, *p_pos, *p_tot;
    cudaGetSymbolAddress(&p_out1, g_out1);
    cudaGetSymbolAddress(&p_pos, g_pos);
    cudaGetSymbolAddress(&p_tot, g_tot);

    const int EB  = E_TOT * 16 / 256;                       // half-warp per edge (exact)
    const int EB2 = (E_TOT * 4 + 255) / 256;                // 4 lanes per edge
    const int NB  = (N_NODES + 255) / 256;

    k_detect<<<1, 32>>>(e32);

    // ---- layer 1 ----
    cudaMemsetAsync(p_out1, 0, sizeof(float4) * (size_t)N_NODES * 16);
    cudaMemsetAsync(p_pos, 0, sizeof(int) * N_NODES);
    cudaMemsetAsync(p_tot, 0, sizeof(int) * N_NODES);

    k_gemm64<<<N_NODES * 16 / 256, 256>>>(x, W1);
    k_sign64<<<EB, 256>>>(e32);
    k_coef<<<NB, 256>>>();
    k_scat64<<<EB, 256>>>(e32);

    // ---- layer 2 ----
    k_gemm16<<<N_NODES * 16 / 256, 256>>>(b1, W2);

    cudaMemsetAsync(p_pos, 0, sizeof(int) * N_NODES);
    cudaMemsetAsync(p_tot, 0, sizeof(int) * N_NODES);
    cudaMemsetAsync(d_out, 0, sizeof(float) * (size_t)N_NODES * OUT_CH);

    k_sign16<<<EB2, 256>>>(e32);
    k_coef<<<NB, 256>>>();
    k_scat16<<<EB2, 256>>>(e32, (float4*)out);
    k_final<<<NB, 256>>>(b2, out);
}